// round 1
// baseline (speedup 1.0000x reference)
#include <cuda_runtime.h>
#include <math.h>

// Fixed problem shapes (from setup_inputs)
#define BB   8
#define TT   64
#define RR   100
#define TH   768
#define IH   1024
#define PP   512

// Scratch for intermediate q [B*T, P] and k [B*R, P]
__device__ float g_q[BB * TT * PP];
__device__ float g_k[BB * RR * PP];

// ---------------- f32x2 helpers (Blackwell packed fp32: 2x FFMA throughput) ---
__device__ __forceinline__ unsigned long long ffma2(unsigned long long a,
                                                    unsigned long long b,
                                                    unsigned long long c) {
    unsigned long long d;
    asm("fma.rn.f32x2 %0, %1, %2, %3;" : "=l"(d) : "l"(a), "l"(b), "l"(c));
    return d;
}
__device__ __forceinline__ unsigned long long splat2(float x) {
    unsigned long long r;
    asm("mov.b64 %0, {%1, %1};" : "=l"(r) : "f"(x));
    return r;
}
__device__ __forceinline__ float2 unpack2(unsigned long long v) {
    float2 f;
    asm("mov.b64 {%0, %1}, %2;" : "=f"(f.x), "=f"(f.y) : "l"(v));
    return f;
}

__device__ __forceinline__ float gelu_exact(float x) {
    // exact GELU: 0.5*x*(1+erf(x/sqrt(2)))
    return 0.5f * x * (1.0f + erff(x * 0.70710678118654752440f));
}

__device__ __forceinline__ float tanh_fast(float x) {
    // tanh(x) = 1 - 2/(exp(2x)+1); __expf -> MUFU.EX2, __fdividef -> MUFU.RCP
    // rel err ~1e-6, saturates correctly for large |x|.
    float u = __expf(2.0f * x);
    return 1.0f - __fdividef(2.0f, u + 1.0f);
}

// ---------------- Kernel 1: fused GEMM + bias + exact GELU --------------------
// One launch does both GEMMs:
//   blocks [0,256)   : q = gelu(encT[512,768] @ Wq[768,512] + bq) -> g_q
//   blocks [256,656) : k = gelu(encI[800,1024] @ Wk[1024,512] + bk) -> g_k
// Tile 32x32x32, 128 threads, per-thread 4x2 microtile with f32x2 row-pairs.
#define GBM 32
#define GBN 32
#define GBK 32

__global__ __launch_bounds__(128) void gemm_gelu_kernel(
    const float* __restrict__ encT, const float* __restrict__ Wq,
    const float* __restrict__ bq,
    const float* __restrict__ encI, const float* __restrict__ Wk,
    const float* __restrict__ bk)
{
    // A tile stored TRANSPOSED (Ast[k][m]) so adjacent rows are contiguous ->
    // ulonglong2 load gives two pre-packed f32x2 "a" operands. Pad 36 keeps
    // 16B alignment per row and breaks store bank conflicts.
    __shared__ __align__(16) float Ast[GBK][GBM + 4];
    __shared__ __align__(16) float Ws[GBK][GBN];

    int bid = blockIdx.x;
    const float* A; const float* W; const float* bias; float* C;
    int K, mt, nt;
    if (bid < 256) {
        A = encT; W = Wq; bias = bq; C = g_q; K = TH;
        mt = bid >> 4; nt = bid & 15;
    } else {
        bid -= 256;
        A = encI; W = Wk; bias = bk; C = g_k; K = IH;
        mt = bid >> 4; nt = bid & 15;     // mt in [0,25) : 800 rows exactly
    }
    const int m0 = mt * GBM;
    const int n0 = nt * GBN;

    const int tid = threadIdx.x;
    const int tx = tid & 15;    // col group: cols tx*2, tx*2+1
    const int ty = tid >> 4;    // row group: rows ty*4 .. ty*4+3

    unsigned long long acc00 = 0ull, acc10 = 0ull;  // col tx*2   : rows (0,1),(2,3)
    unsigned long long acc01 = 0ull, acc11 = 0ull;  // col tx*2+1

    for (int k0 = 0; k0 < K; k0 += GBK) {
        // Load A tile (32x32 = 1024 floats), transpose into Ast
        #pragma unroll
        for (int ph = 0; ph < 2; ph++) {
            int flat = ph * 512 + tid * 4;
            int r = flat >> 5, c = flat & 31;
            float4 v = *(const float4*)&A[(m0 + r) * K + k0 + c];
            Ast[c + 0][r] = v.x; Ast[c + 1][r] = v.y;
            Ast[c + 2][r] = v.z; Ast[c + 3][r] = v.w;
        }
        // Load W tile (32x32) straight
        #pragma unroll
        for (int ph = 0; ph < 2; ph++) {
            int flat = ph * 512 + tid * 4;
            int kk = flat >> 5, n = flat & 31;
            *(float4*)&Ws[kk][n] = *(const float4*)&W[(k0 + kk) * PP + n0 + n];
        }
        __syncthreads();

        #pragma unroll
        for (int kk = 0; kk < GBK; kk++) {
            ulonglong2 aa = *(const ulonglong2*)&Ast[kk][ty * 4];  // rows (r0,r1),(r2,r3)
            float2 bv = *(const float2*)&Ws[kk][tx * 2];
            unsigned long long b0 = splat2(bv.x);
            unsigned long long b1 = splat2(bv.y);
            acc00 = ffma2(aa.x, b0, acc00);
            acc10 = ffma2(aa.y, b0, acc10);
            acc01 = ffma2(aa.x, b1, acc01);
            acc11 = ffma2(aa.y, b1, acc11);
        }
        __syncthreads();
    }

    // Epilogue: unpack, bias, exact GELU, store float2 per row
    float2 c00 = unpack2(acc00), c10 = unpack2(acc10);
    float2 c01 = unpack2(acc01), c11 = unpack2(acc11);
    float bz0 = bias[n0 + tx * 2];
    float bz1 = bias[n0 + tx * 2 + 1];

    float2 o;
    int base = (m0 + ty * 4) * PP + n0 + tx * 2;
    o.x = gelu_exact(c00.x + bz0); o.y = gelu_exact(c01.x + bz1);
    *(float2*)&C[base] = o;
    o.x = gelu_exact(c00.y + bz0); o.y = gelu_exact(c01.y + bz1);
    *(float2*)&C[base + PP] = o;
    o.x = gelu_exact(c10.x + bz0); o.y = gelu_exact(c11.x + bz1);
    *(float2*)&C[base + 2 * PP] = o;
    o.x = gelu_exact(c10.y + bz0); o.y = gelu_exact(c11.y + bz1);
    *(float2*)&C[base + 3 * PP] = o;
}

// ---------------- Kernel 2: fusion + tanh + weighted reduce -------------------
// grid = B * (T/4) = 128 blocks, 256 threads (8 warps).
// Block stages 4 q rows + w in smem; each warp handles (t_local, r) tasks,
// one warp-reduction per output logit.
__global__ __launch_bounds__(256) void fusion_kernel(
    const float* __restrict__ mask, const float* __restrict__ w,
    const float* __restrict__ bptr, float* __restrict__ out)
{
    __shared__ __align__(16) float qs[4 * PP];
    __shared__ __align__(16) float ws[PP];

    const int tid = threadIdx.x;
    const int b  = blockIdx.x >> 4;
    const int t0 = (blockIdx.x & 15) * 4;

    for (int i = tid; i < 4 * PP; i += 256) {
        int tl = i >> 9, p = i & (PP - 1);
        qs[i] = g_q[(b * TT + t0 + tl) * PP + p];
    }
    for (int i = tid; i < PP; i += 256) ws[i] = w[i];
    __syncthreads();

    const float bb = bptr[0];
    const int warp = tid >> 5, lane = tid & 31;
    const float4* qs4 = (const float4*)qs;
    const float4* ws4 = (const float4*)ws;

    // 400 (tl,r) tasks, 8 warps -> 50 tasks each
    for (int task = warp; task < 4 * RR; task += 8) {
        int r = task >> 2, tl = task & 3;
        const float4* k4 = (const float4*)&g_k[(b * RR + r) * PP];
        float acc = 0.0f;
        #pragma unroll
        for (int j = 0; j < 4; j++) {
            int idx = lane + j * 32;           // float4 index, p = idx*4
            float4 kv = k4[idx];
            float4 qv = qs4[tl * 128 + idx];
            float4 wv = ws4[idx];
            acc += tanh_fast(qv.x + kv.x) * wv.x;
            acc += tanh_fast(qv.y + kv.y) * wv.y;
            acc += tanh_fast(qv.z + kv.z) * wv.z;
            acc += tanh_fast(qv.w + kv.w) * wv.w;
        }
        #pragma unroll
        for (int off = 16; off; off >>= 1)
            acc += __shfl_xor_sync(0xffffffffu, acc, off);
        if (lane == 0) {
            int oi = (b * TT + t0 + tl) * RR + r;
            out[oi] = acc + bb + mask[oi];
        }
    }
}

// ---------------- launch ------------------------------------------------------
extern "C" void kernel_launch(void* const* d_in, const int* in_sizes, int n_in,
                              void* d_out, int out_size) {
    const float* encT = (const float*)d_in[0];
    const float* encI = (const float*)d_in[1];
    const float* mask = (const float*)d_in[2];
    const float* Wq   = (const float*)d_in[3];
    const float* bq   = (const float*)d_in[4];
    const float* Wk   = (const float*)d_in[5];
    const float* bk   = (const float*)d_in[6];
    const float* w    = (const float*)d_in[7];
    const float* bp   = (const float*)d_in[8];
    float* out = (float*)d_out;

    // 256 q-blocks + 400 k-blocks in one launch for wave balance
    gemm_gelu_kernel<<<656, 128>>>(encT, Wq, bq, encI, Wk, bk);
    fusion_kernel<<<BB * (TT / 4), 256>>>(mask, w, bp, out);
}

// round 4
// speedup vs baseline: 2.1545x; 2.1545x over previous
#include <cuda_runtime.h>
#include <math.h>

// Fixed problem shapes (from setup_inputs)
#define BB   8
#define TT   64
#define RR   100
#define TH   768
#define IH   1024
#define PP   512

// Scratch for intermediate q [B*T, P] and k [B*R, P]
__device__ float g_q[BB * TT * PP];
__device__ float g_k[BB * RR * PP];

// ---------------- f32x2 helpers (Blackwell packed fp32: 2x FFMA throughput) ---
__device__ __forceinline__ unsigned long long ffma2(unsigned long long a,
                                                    unsigned long long b,
                                                    unsigned long long c) {
    unsigned long long d;
    asm("fma.rn.f32x2 %0, %1, %2, %3;" : "=l"(d) : "l"(a), "l"(b), "l"(c));
    return d;
}
__device__ __forceinline__ unsigned long long splat2(float x) {
    unsigned long long r;
    asm("mov.b64 %0, {%1, %1};" : "=l"(r) : "f"(x));
    return r;
}
__device__ __forceinline__ float2 unpack2(unsigned long long v) {
    float2 f;
    asm("mov.b64 {%0, %1}, %2;" : "=f"(f.x), "=f"(f.y) : "l"(v));
    return f;
}

__device__ __forceinline__ float gelu_exact(float x) {
    return 0.5f * x * (1.0f + erff(x * 0.70710678118654752440f));
}

__device__ __forceinline__ float tanh_fast(float x) {
    // tanh(x) = 1 - 2/(exp(2x)+1); rel err ~1e-6.
    float u = __expf(2.0f * x);
    return 1.0f - __fdividef(2.0f, u + 1.0f);
}

// ---------------- Kernel 1: fused GEMM + bias + exact GELU --------------------
// blocks [0,256)   : q = gelu(encT[512,768] @ Wq + bq) -> g_q
// blocks [256,656) : k = gelu(encI[800,1024] @ Wk + bk) -> g_k
// 32x32x32 tile, 128 threads, 4x2 f32x2 microtile, reg-prefetch double buffer.
#define GBM 32
#define GBN 32
#define GBK 32

__global__ __launch_bounds__(128) void gemm_gelu_kernel(
    const float* __restrict__ encT, const float* __restrict__ Wq,
    const float* __restrict__ bq,
    const float* __restrict__ encI, const float* __restrict__ Wk,
    const float* __restrict__ bk)
{
    // A tile transposed: Ast[buf][k][m]; pad 4 keeps rows 16B-aligned so the
    // 4-row read is a single LDS.128 (broadcast across the warp).
    __shared__ __align__(16) float Ast[2][GBK][GBM + 4];
    __shared__ __align__(16) float Ws[2][GBK][GBN];

    int bid = blockIdx.x;
    const float* A; const float* W; const float* bias; float* C;
    int K, mt, nt;
    if (bid < 256) {
        A = encT; W = Wq; bias = bq; C = g_q; K = TH;
        mt = bid >> 4; nt = bid & 15;
    } else {
        bid -= 256;
        A = encI; W = Wk; bias = bk; C = g_k; K = IH;
        mt = bid >> 4; nt = bid & 15;     // mt in [0,25): 800 rows exact
    }
    const int m0 = mt * GBM;
    const int n0 = nt * GBN;

    const int tid = threadIdx.x;
    const int tx = tid & 15;    // col pair: n = tx*2, tx*2+1
    const int ty = tid >> 4;    // row group: m = ty*4 .. ty*4+3

    // per-thread tile-load coordinates (2 float4 per tile each for A and W)
    const int ar0 = (tid * 4) >> 5,  ac0 = (tid * 4) & 31;        // phase 0
    const int ar1 = ((512 + tid * 4) >> 5), ac1 = (tid * 4) & 31; // phase 1

    unsigned long long acc00 = 0ull, acc10 = 0ull;
    unsigned long long acc01 = 0ull, acc11 = 0ull;

    const int niter = K / GBK;
    float4 pa0, pa1, pw0, pw1;

    // prefetch tile 0
    {
        const int k0 = 0;
        pa0 = *(const float4*)&A[(m0 + ar0) * K + k0 + ac0];
        pa1 = *(const float4*)&A[(m0 + ar1) * K + k0 + ac1];
        pw0 = *(const float4*)&W[(k0 + ar0) * PP + n0 + ac0];
        pw1 = *(const float4*)&W[(k0 + ar1) * PP + n0 + ac1];
    }
    // store tile 0 into buffer 0
    {
        Ast[0][ac0 + 0][ar0] = pa0.x; Ast[0][ac0 + 1][ar0] = pa0.y;
        Ast[0][ac0 + 2][ar0] = pa0.z; Ast[0][ac0 + 3][ar0] = pa0.w;
        Ast[0][ac1 + 0][ar1] = pa1.x; Ast[0][ac1 + 1][ar1] = pa1.y;
        Ast[0][ac1 + 2][ar1] = pa1.z; Ast[0][ac1 + 3][ar1] = pa1.w;
        *(float4*)&Ws[0][ar0][ac0] = pw0;
        *(float4*)&Ws[0][ar1][ac1] = pw1;
    }

    for (int it = 0; it < niter; it++) {
        __syncthreads();
        const int cur = it & 1;

        // prefetch next tile into registers (overlaps with compute below)
        const bool more = (it + 1) < niter;
        if (more) {
            const int k0 = (it + 1) * GBK;
            pa0 = *(const float4*)&A[(m0 + ar0) * K + k0 + ac0];
            pa1 = *(const float4*)&A[(m0 + ar1) * K + k0 + ac1];
            pw0 = *(const float4*)&W[(k0 + ar0) * PP + n0 + ac0];
            pw1 = *(const float4*)&W[(k0 + ar1) * PP + n0 + ac1];
        }

        #pragma unroll
        for (int kk = 0; kk < GBK; kk++) {
            ulonglong2 aa = *(const ulonglong2*)&Ast[cur][kk][ty * 4];
            float2 bv = *(const float2*)&Ws[cur][kk][tx * 2];
            unsigned long long b0 = splat2(bv.x);
            unsigned long long b1 = splat2(bv.y);
            acc00 = ffma2(aa.x, b0, acc00);
            acc10 = ffma2(aa.y, b0, acc10);
            acc01 = ffma2(aa.x, b1, acc01);
            acc11 = ffma2(aa.y, b1, acc11);
        }

        if (more) {
            const int nxt = cur ^ 1;
            Ast[nxt][ac0 + 0][ar0] = pa0.x; Ast[nxt][ac0 + 1][ar0] = pa0.y;
            Ast[nxt][ac0 + 2][ar0] = pa0.z; Ast[nxt][ac0 + 3][ar0] = pa0.w;
            Ast[nxt][ac1 + 0][ar1] = pa1.x; Ast[nxt][ac1 + 1][ar1] = pa1.y;
            Ast[nxt][ac1 + 2][ar1] = pa1.z; Ast[nxt][ac1 + 3][ar1] = pa1.w;
            *(float4*)&Ws[nxt][ar0][ac0] = pw0;
            *(float4*)&Ws[nxt][ar1][ac1] = pw1;
        }
    }

    // Epilogue: bias + exact GELU, float2 stores
    float2 c00 = unpack2(acc00), c10 = unpack2(acc10);
    float2 c01 = unpack2(acc01), c11 = unpack2(acc11);
    float bz0 = bias[n0 + tx * 2];
    float bz1 = bias[n0 + tx * 2 + 1];

    float2 o;
    int base = (m0 + ty * 4) * PP + n0 + tx * 2;
    o.x = gelu_exact(c00.x + bz0); o.y = gelu_exact(c01.x + bz1);
    *(float2*)&C[base] = o;
    o.x = gelu_exact(c00.y + bz0); o.y = gelu_exact(c01.y + bz1);
    *(float2*)&C[base + PP] = o;
    o.x = gelu_exact(c10.x + bz0); o.y = gelu_exact(c11.x + bz1);
    *(float2*)&C[base + 2 * PP] = o;
    o.x = gelu_exact(c10.y + bz0); o.y = gelu_exact(c11.y + bz1);
    *(float2*)&C[base + 3 * PP] = o;
}

// ---------------- Kernel 2: fusion + tanh + weighted reduce -------------------
// grid = B*T = 512 blocks, 256 threads (8 warps). One (b,t) per block.
// q row + w live in REGISTERS (each lane touches the same 16 floats of each
// across every r). Each warp owns r = warp, warp+8, ...; k row loads are
// software-pipelined one r ahead to hide L2 latency.
__global__ __launch_bounds__(256) void fusion_kernel(
    const float* __restrict__ mask, const float* __restrict__ w,
    const float* __restrict__ bptr, float* __restrict__ out)
{
    const int b = blockIdx.x >> 6;          // /TT
    const int t = blockIdx.x & 63;          // %TT
    const int warp = threadIdx.x >> 5, lane = threadIdx.x & 31;

    const float4* q4 = (const float4*)&g_q[(b * TT + t) * PP];
    const float4* w4 = (const float4*)w;
    const float4* kbase = (const float4*)&g_k[(size_t)b * RR * PP];

    float4 qv[4], wv[4];
    #pragma unroll
    for (int j = 0; j < 4; j++) {
        qv[j] = q4[lane + j * 32];
        wv[j] = w4[lane + j * 32];
    }

    const float bb = bptr[0];
    const int obase = (b * TT + t) * RR;

    // prefetch first k row for this warp
    float4 kv[4];
    #pragma unroll
    for (int j = 0; j < 4; j++)
        kv[j] = kbase[warp * 128 + lane + j * 32];

    for (int r = warp; r < RR; r += 8) {
        float4 nv[4];
        const int rn = r + 8;
        if (rn < RR) {
            #pragma unroll
            for (int j = 0; j < 4; j++)
                nv[j] = kbase[rn * 128 + lane + j * 32];
        }

        float acc = 0.0f;
        #pragma unroll
        for (int j = 0; j < 4; j++) {
            acc += tanh_fast(qv[j].x + kv[j].x) * wv[j].x;
            acc += tanh_fast(qv[j].y + kv[j].y) * wv[j].y;
            acc += tanh_fast(qv[j].z + kv[j].z) * wv[j].z;
            acc += tanh_fast(qv[j].w + kv[j].w) * wv[j].w;
        }
        #pragma unroll
        for (int off = 16; off; off >>= 1)
            acc += __shfl_xor_sync(0xffffffffu, acc, off);
        if (lane == 0)
            out[obase + r] = acc + bb + mask[obase + r];

        #pragma unroll
        for (int j = 0; j < 4; j++) kv[j] = nv[j];
    }
}

// ---------------- launch ------------------------------------------------------
extern "C" void kernel_launch(void* const* d_in, const int* in_sizes, int n_in,
                              void* d_out, int out_size) {
    const float* encT = (const float*)d_in[0];
    const float* encI = (const float*)d_in[1];
    const float* mask = (const float*)d_in[2];
    const float* Wq   = (const float*)d_in[3];
    const float* bq   = (const float*)d_in[4];
    const float* Wk   = (const float*)d_in[5];
    const float* bk   = (const float*)d_in[6];
    const float* w    = (const float*)d_in[7];
    const float* bp   = (const float*)d_in[8];
    float* out = (float*)d_out;

    gemm_gelu_kernel<<<656, 128>>>(encT, Wq, bq, encI, Wk, bk);
    fusion_kernel<<<BB * TT, 256>>>(mask, w, bp, out);
}